// round 2
// baseline (speedup 1.0000x reference)
#include <cuda_runtime.h>
#include <cuda_bf16.h>

// Shapes (fixed per reference)
#define S_DIM   64
#define C_DIM   384
#define HW      3136          // 56*56
#define HW4     784           // HW/4 (float4 quads per channel plane)
#define CHW     (C_DIM * HW)  // 1204224 floats per frame
#define S_TOP   16
#define CNUM    48            // C_DIM / 8

// Scratch (no device allocation allowed)
__device__ float g_xg[S_DIM * C_DIM];     // per-frame, per-channel means
__device__ float g_convk[C_DIM * 3];      // per-channel temporal kernel (softmaxed)

// ---------------------------------------------------------------------------
// Kernel 1: global average pool. One block per (s,c) plane of 3136 floats.
// ---------------------------------------------------------------------------
__global__ void pool_kernel(const float* __restrict__ x) {
    int plane = blockIdx.x;                 // = s*C_DIM + c (x is (s,c,h,w) contiguous)
    const float4* p = reinterpret_cast<const float4*>(x + (size_t)plane * HW);
    float sum = 0.f;
    for (int i = threadIdx.x; i < HW4; i += blockDim.x) {
        float4 v = p[i];
        sum += (v.x + v.y) + (v.z + v.w);
    }
    // warp reduce
    #pragma unroll
    for (int off = 16; off > 0; off >>= 1)
        sum += __shfl_down_sync(0xFFFFFFFFu, sum, off);
    __shared__ float warp_sums[4];          // 128 threads = 4 warps
    int lane = threadIdx.x & 31, wid = threadIdx.x >> 5;
    if (lane == 0) warp_sums[wid] = sum;
    __syncthreads();
    if (threadIdx.x == 0) {
        float t = warp_sums[0] + warp_sums[1] + warp_sums[2] + warp_sums[3];
        g_xg[plane] = t * (1.0f / (float)HW);
    }
}

// ---------------------------------------------------------------------------
// Kernel 2: scores -> stable top-16 (temporal order) -> per-channel MLP ->
// softmax temporal kernel. Single block, 384 threads. Tiny.
// ---------------------------------------------------------------------------
__global__ void mlp_kernel(const float* __restrict__ w_lin,
                           const float* __restrict__ w1,
                           const float* __restrict__ bn_gamma,
                           const float* __restrict__ bn_beta,
                           const float* __restrict__ bn_mean,
                           const float* __restrict__ bn_var,
                           const float* __restrict__ w2) {
    __shared__ float sc[S_DIM];
    __shared__ int   idx[S_TOP];
    int t = threadIdx.x;

    // scores: xgs[s] = dot(xg[s,:], w_lin)
    if (t < S_DIM) {
        float acc = 0.f;
        const float* row = g_xg + t * C_DIM;
        for (int c = 0; c < C_DIM; c++) acc = fmaf(row[c], w_lin[c], acc);
        sc[t] = acc;
    }
    __syncthreads();

    // stable top-16 by descending score, collected in ascending index order.
    // rank(i) = #{j : sc[j] > sc[i]  or (sc[j]==sc[i] and j < i)}  (stable argsort)
    if (t == 0) {
        int n = 0;
        for (int i = 0; i < S_DIM && n < S_TOP; i++) {
            int rank = 0;
            float si = sc[i];
            for (int j = 0; j < S_DIM; j++) {
                float sj = sc[j];
                if (sj > si || (sj == si && j < i)) rank++;
            }
            if (rank < S_TOP) idx[n++] = i;
        }
    }
    __syncthreads();

    if (t < C_DIM) {
        // sls[j] = xg[idx[j], c]
        float sls[S_TOP];
        #pragma unroll
        for (int j = 0; j < S_TOP; j++) sls[j] = g_xg[idx[j] * C_DIM + t];

        float l0 = 0.f, l1 = 0.f, l2 = 0.f;
        #pragma unroll 4
        for (int k = 0; k < 2 * S_TOP; k++) {
            float acc = 0.f;
            const float* w1row = w1 + k * S_TOP;
            #pragma unroll
            for (int j = 0; j < S_TOP; j++) acc = fmaf(sls[j], w1row[j], acc);
            // BN (eval mode) + ReLU
            float scale = bn_gamma[k] * rsqrtf(bn_var[k] + 1e-5f);
            acc = fmaf(acc - bn_mean[k], scale, bn_beta[k]);
            acc = fmaxf(acc, 0.f);
            l0 = fmaf(acc, w2[0 * 2 * S_TOP + k], l0);
            l1 = fmaf(acc, w2[1 * 2 * S_TOP + k], l1);
            l2 = fmaf(acc, w2[2 * 2 * S_TOP + k], l2);
        }
        float mx = fmaxf(l0, fmaxf(l1, l2));
        float e0 = __expf(l0 - mx), e1 = __expf(l1 - mx), e2 = __expf(l2 - mx);
        float inv = 1.0f / (e0 + e1 + e2);
        g_convk[t * 3 + 0] = e0 * inv;
        g_convk[t * 3 + 1] = e1 * inv;
        g_convk[t * 3 + 2] = e2 * inv;
    }
}

// ---------------------------------------------------------------------------
// Kernel 3: channel shift + depthwise temporal conv (k=3, zero pad).
// One thread per (channel, float4 quad). Sliding 3-register window over s:
// each x element read exactly once, fully coalesced 16B accesses.
// ---------------------------------------------------------------------------
__global__ void conv_kernel(const float* __restrict__ x, float* __restrict__ out) {
    int tid = blockIdx.x * blockDim.x + threadIdx.x;
    if (tid >= C_DIM * HW4) return;
    int c = tid / HW4;
    int q = tid - c * HW4;
    size_t base = (size_t)c * HW + (size_t)q * 4;   // float index, 16B aligned

    // channel shift: c<48 -> read x[s+1]; 48<=c<96 -> x[s-1]; else x[s]
    int d = (c < CNUM) ? 1 : ((c < 2 * CNUM) ? -1 : 0);

    float k0 = g_convk[c * 3 + 0];
    float k1 = g_convk[c * 3 + 1];
    float k2 = g_convk[c * 3 + 2];

    const float4 zero4 = make_float4(0.f, 0.f, 0.f, 0.f);
    auto ld = [&](int t) -> float4 {
        int ts = t + d;
        if ((unsigned)t < (unsigned)S_DIM && (unsigned)ts < (unsigned)S_DIM)
            return *reinterpret_cast<const float4*>(x + (size_t)ts * CHW + base);
        return zero4;
    };

    float4 ym = zero4;        // y(t-1)
    float4 yc = ld(0);        // y(t)
    #pragma unroll 4
    for (int t = 0; t < S_DIM; t++) {
        float4 yp = ld(t + 1);   // y(t+1); returns zero beyond the end
        float4 o;
        o.x = fmaf(k0, ym.x, fmaf(k1, yc.x, k2 * yp.x));
        o.y = fmaf(k0, ym.y, fmaf(k1, yc.y, k2 * yp.y));
        o.z = fmaf(k0, ym.z, fmaf(k1, yc.z, k2 * yp.z));
        o.w = fmaf(k0, ym.w, fmaf(k1, yc.w, k2 * yp.w));
        *reinterpret_cast<float4*>(out + (size_t)t * CHW + base) = o;
        ym = yc; yc = yp;
    }
}

// ---------------------------------------------------------------------------
extern "C" void kernel_launch(void* const* d_in, const int* in_sizes, int n_in,
                              void* d_out, int out_size) {
    const float* x        = (const float*)d_in[0];
    const float* w_lin    = (const float*)d_in[1];
    const float* w1       = (const float*)d_in[2];
    const float* bn_gamma = (const float*)d_in[3];
    const float* bn_beta  = (const float*)d_in[4];
    const float* bn_mean  = (const float*)d_in[5];
    const float* bn_var   = (const float*)d_in[6];
    const float* w2       = (const float*)d_in[7];
    float* out            = (float*)d_out;

    pool_kernel<<<S_DIM * C_DIM, 128>>>(x);
    mlp_kernel<<<1, C_DIM>>>(w_lin, w1, bn_gamma, bn_beta, bn_mean, bn_var, w2);
    int threads = 256;
    int total = C_DIM * HW4;
    conv_kernel<<<(total + threads - 1) / threads, threads>>>(x, out);
}

// round 3
// speedup vs baseline: 1.0611x; 1.0611x over previous
#include <cuda_runtime.h>
#include <cuda_bf16.h>

// Shapes (fixed per reference)
#define S_DIM   64
#define C_DIM   384
#define HW      3136          // 56*56
#define HW4     784           // HW/4 (float4 quads per channel plane)
#define CHW     (C_DIM * HW)  // 1204224 floats per frame
#define S_TOP   16
#define CNUM    48            // C_DIM / 8

#define SEG     16            // frames per conv segment
#define NSEG    (S_DIM / SEG) // 4
#define NQUADS  (C_DIM * HW4) // 301056 (c, quad) tasks

// Scratch (no device allocation allowed)
__device__ float g_xg[S_DIM * C_DIM];     // per-frame, per-channel means
__device__ float g_convk[C_DIM * 3];      // per-channel temporal kernel (softmaxed)

// ---------------------------------------------------------------------------
// Kernel 1: global average pool. One block per (s,c) plane of 3136 floats.
// ---------------------------------------------------------------------------
__global__ void pool_kernel(const float* __restrict__ x) {
    int plane = blockIdx.x;                 // = s*C_DIM + c (x is (s,c,h,w) contiguous)
    const float4* p = reinterpret_cast<const float4*>(x + (size_t)plane * HW);
    float sum = 0.f;
    for (int i = threadIdx.x; i < HW4; i += blockDim.x) {
        float4 v = __ldcs(p + i);           // streaming read: evict-first
        sum += (v.x + v.y) + (v.z + v.w);
    }
    // warp reduce
    #pragma unroll
    for (int off = 16; off > 0; off >>= 1)
        sum += __shfl_down_sync(0xFFFFFFFFu, sum, off);
    __shared__ float warp_sums[4];          // 128 threads = 4 warps
    int lane = threadIdx.x & 31, wid = threadIdx.x >> 5;
    if (lane == 0) warp_sums[wid] = sum;
    __syncthreads();
    if (threadIdx.x == 0) {
        float t = warp_sums[0] + warp_sums[1] + warp_sums[2] + warp_sums[3];
        g_xg[plane] = t * (1.0f / (float)HW);
    }
}

// ---------------------------------------------------------------------------
// Kernel 2: scores -> stable top-16 (temporal order) -> per-channel MLP ->
// softmax temporal kernel. Single block, 384 threads. Tiny.
// ---------------------------------------------------------------------------
__global__ void mlp_kernel(const float* __restrict__ w_lin,
                           const float* __restrict__ w1,
                           const float* __restrict__ bn_gamma,
                           const float* __restrict__ bn_beta,
                           const float* __restrict__ bn_mean,
                           const float* __restrict__ bn_var,
                           const float* __restrict__ w2) {
    __shared__ float sc[S_DIM];
    __shared__ int   idx[S_TOP];
    int t = threadIdx.x;

    // scores: xgs[s] = dot(xg[s,:], w_lin)
    if (t < S_DIM) {
        float acc = 0.f;
        const float* row = g_xg + t * C_DIM;
        for (int c = 0; c < C_DIM; c++) acc = fmaf(row[c], w_lin[c], acc);
        sc[t] = acc;
    }
    __syncthreads();

    // stable top-16 by descending score, collected in ascending index order.
    // rank(i) = #{j : sc[j] > sc[i]  or (sc[j]==sc[i] and j < i)}  (stable argsort)
    if (t == 0) {
        int n = 0;
        for (int i = 0; i < S_DIM && n < S_TOP; i++) {
            int rank = 0;
            float si = sc[i];
            for (int j = 0; j < S_DIM; j++) {
                float sj = sc[j];
                if (sj > si || (sj == si && j < i)) rank++;
            }
            if (rank < S_TOP) idx[n++] = i;
        }
    }
    __syncthreads();

    if (t < C_DIM) {
        // sls[j] = xg[idx[j], c]
        float sls[S_TOP];
        #pragma unroll
        for (int j = 0; j < S_TOP; j++) sls[j] = g_xg[idx[j] * C_DIM + t];

        float l0 = 0.f, l1 = 0.f, l2 = 0.f;
        #pragma unroll 4
        for (int k = 0; k < 2 * S_TOP; k++) {
            float acc = 0.f;
            const float* w1row = w1 + k * S_TOP;
            #pragma unroll
            for (int j = 0; j < S_TOP; j++) acc = fmaf(sls[j], w1row[j], acc);
            // BN (eval mode) + ReLU
            float scale = bn_gamma[k] * rsqrtf(bn_var[k] + 1e-5f);
            acc = fmaf(acc - bn_mean[k], scale, bn_beta[k]);
            acc = fmaxf(acc, 0.f);
            l0 = fmaf(acc, w2[0 * 2 * S_TOP + k], l0);
            l1 = fmaf(acc, w2[1 * 2 * S_TOP + k], l1);
            l2 = fmaf(acc, w2[2 * 2 * S_TOP + k], l2);
        }
        float mx = fmaxf(l0, fmaxf(l1, l2));
        float e0 = __expf(l0 - mx), e1 = __expf(l1 - mx), e2 = __expf(l2 - mx);
        float inv = 1.0f / (e0 + e1 + e2);
        g_convk[t * 3 + 0] = e0 * inv;
        g_convk[t * 3 + 1] = e1 * inv;
        g_convk[t * 3 + 2] = e2 * inv;
    }
}

// ---------------------------------------------------------------------------
// Kernel 3: channel shift + depthwise temporal conv (k=3, zero pad).
// One thread per (segment of SEG frames, channel, float4 quad). Sliding
// 3-register window over s within the segment; per thread: SEG+2 coalesced
// float4 reads, SEG coalesced float4 writes. Segmentation keeps per-CTA work
// small so one slow CTA cannot dominate the wave (B300 multi-CTA spread).
// ---------------------------------------------------------------------------
__global__ void conv_kernel(const float* __restrict__ x, float* __restrict__ out) {
    int tid = blockIdx.x * blockDim.x + threadIdx.x;
    if (tid >= NSEG * NQUADS) return;
    int seg  = tid / NQUADS;                 // slowest: segments spread across waves
    int task = tid - seg * NQUADS;
    int c = task / HW4;
    int q = task - c * HW4;
    size_t base = (size_t)c * HW + (size_t)q * 4;   // float index, 16B aligned
    int t0 = seg * SEG;

    // channel shift: c<48 -> read x[s+1]; 48<=c<96 -> x[s-1]; else x[s]
    int d = (c < CNUM) ? 1 : ((c < 2 * CNUM) ? -1 : 0);

    float k0 = g_convk[c * 3 + 0];
    float k1 = g_convk[c * 3 + 1];
    float k2 = g_convk[c * 3 + 2];

    const float4 zero4 = make_float4(0.f, 0.f, 0.f, 0.f);
    auto ld = [&](int t) -> float4 {
        int ts = t + d;
        if ((unsigned)t < (unsigned)S_DIM && (unsigned)ts < (unsigned)S_DIM)
            return __ldcs(reinterpret_cast<const float4*>(x + (size_t)ts * CHW + base));
        return zero4;
    };

    float4 ym = ld(t0 - 1);   // y(t-1); zero when t0==0
    float4 yc = ld(t0);       // y(t)
    #pragma unroll
    for (int i = 0; i < SEG; i++) {
        int t = t0 + i;
        float4 yp = ld(t + 1);   // y(t+1); zero beyond the end
        float4 o;
        o.x = fmaf(k0, ym.x, fmaf(k1, yc.x, k2 * yp.x));
        o.y = fmaf(k0, ym.y, fmaf(k1, yc.y, k2 * yp.y));
        o.z = fmaf(k0, ym.z, fmaf(k1, yc.z, k2 * yp.z));
        o.w = fmaf(k0, ym.w, fmaf(k1, yc.w, k2 * yp.w));
        __stcs(reinterpret_cast<float4*>(out + (size_t)t * CHW + base), o);
        ym = yc; yc = yp;
    }
}

// ---------------------------------------------------------------------------
extern "C" void kernel_launch(void* const* d_in, const int* in_sizes, int n_in,
                              void* d_out, int out_size) {
    const float* x        = (const float*)d_in[0];
    const float* w_lin    = (const float*)d_in[1];
    const float* w1       = (const float*)d_in[2];
    const float* bn_gamma = (const float*)d_in[3];
    const float* bn_beta  = (const float*)d_in[4];
    const float* bn_mean  = (const float*)d_in[5];
    const float* bn_var   = (const float*)d_in[6];
    const float* w2       = (const float*)d_in[7];
    float* out            = (float*)d_out;

    pool_kernel<<<S_DIM * C_DIM, 128>>>(x);
    mlp_kernel<<<1, C_DIM>>>(w_lin, w1, bn_gamma, bn_beta, bn_mean, bn_var, w2);
    int threads = 256;
    int total = NSEG * NQUADS;
    conv_kernel<<<(total + threads - 1) / threads, threads>>>(x, out);
}

// round 4
// speedup vs baseline: 1.2175x; 1.1474x over previous
#include <cuda_runtime.h>
#include <cuda_bf16.h>

// Shapes (fixed per reference)
#define S_DIM   64
#define C_DIM   384
#define HW      3136          // 56*56
#define HW4     784           // HW/4 (float4 quads per channel plane)
#define CHW     (C_DIM * HW)  // 1204224 floats per frame
#define S_TOP   16
#define CNUM    48            // C_DIM / 8

#define SEG     16            // frames per conv segment
#define NSEG    (S_DIM / SEG) // 4
#define NQUADS  (C_DIM * HW4) // 301056 (c, quad) tasks

// Scratch (no device allocation allowed)
__device__ float g_xg[S_DIM * C_DIM];     // per-frame, per-channel means
__device__ float g_convk[C_DIM * 3];      // per-channel temporal kernel (softmaxed)

// ---------------------------------------------------------------------------
// Kernel 1: global average pool. One block per (s,c) plane of 3136 floats.
// ---------------------------------------------------------------------------
__global__ void pool_kernel(const float* __restrict__ x) {
    int plane = blockIdx.x;                 // = s*C_DIM + c (x is (s,c,h,w) contiguous)
    const float4* p = reinterpret_cast<const float4*>(x + (size_t)plane * HW);
    float sum = 0.f;
    for (int i = threadIdx.x; i < HW4; i += blockDim.x) {
        float4 v = __ldcs(p + i);           // streaming read: evict-first
        sum += (v.x + v.y) + (v.z + v.w);
    }
    // warp reduce
    #pragma unroll
    for (int off = 16; off > 0; off >>= 1)
        sum += __shfl_down_sync(0xFFFFFFFFu, sum, off);
    __shared__ float warp_sums[4];          // 128 threads = 4 warps
    int lane = threadIdx.x & 31, wid = threadIdx.x >> 5;
    if (lane == 0) warp_sums[wid] = sum;
    __syncthreads();
    if (threadIdx.x == 0) {
        float t = warp_sums[0] + warp_sums[1] + warp_sums[2] + warp_sums[3];
        g_xg[plane] = t * (1.0f / (float)HW);
    }
}

// ---------------------------------------------------------------------------
// Kernel 2: scores -> stable top-16 (temporal order) -> per-channel MLP ->
// softmax temporal kernel. Single block, 384 threads (12 warps).
// Parallelized: warp-per-frame scores, thread-per-frame ranks.
// ---------------------------------------------------------------------------
__global__ void mlp_kernel(const float* __restrict__ w_lin,
                           const float* __restrict__ w1,
                           const float* __restrict__ bn_gamma,
                           const float* __restrict__ bn_beta,
                           const float* __restrict__ bn_mean,
                           const float* __restrict__ bn_var,
                           const float* __restrict__ w2) {
    __shared__ float sc[S_DIM];
    __shared__ int   flag[S_DIM];
    __shared__ int   idx[S_TOP];
    int t    = threadIdx.x;
    int lane = t & 31;
    int wid  = t >> 5;                      // 0..11

    // --- scores: xgs[s] = dot(xg[s,:], w_lin); one warp per frame ---
    for (int s = wid; s < S_DIM; s += 12) {
        const float* row = g_xg + s * C_DIM;
        float acc = 0.f;
        #pragma unroll
        for (int j = 0; j < C_DIM / 32; j++) {          // 12 elements per lane
            int c = lane + j * 32;
            acc = fmaf(row[c], w_lin[c], acc);
        }
        #pragma unroll
        for (int off = 16; off > 0; off >>= 1)
            acc += __shfl_down_sync(0xFFFFFFFFu, acc, off);
        if (lane == 0) sc[s] = acc;
    }
    __syncthreads();

    // --- stable rank: rank(i) = #{j : sc[j] > sc[i] or (== and j < i)} ---
    if (t < S_DIM) {
        float si = sc[t];
        int rank = 0;
        #pragma unroll 8
        for (int j = 0; j < S_DIM; j++) {
            float sj = sc[j];
            rank += (sj > si || (sj == si && j < t)) ? 1 : 0;
        }
        flag[t] = (rank < S_TOP) ? 1 : 0;
    }
    __syncthreads();
    if (t == 0) {                            // trivial 64-iter compaction
        int n = 0;
        for (int i = 0; i < S_DIM; i++)
            if (flag[i] && n < S_TOP) idx[n++] = i;
    }
    __syncthreads();

    // --- per-channel kernel-generating MLP ---
    if (t < C_DIM) {
        float sls[S_TOP];
        #pragma unroll
        for (int j = 0; j < S_TOP; j++) sls[j] = g_xg[idx[j] * C_DIM + t];

        float l0 = 0.f, l1 = 0.f, l2 = 0.f;
        #pragma unroll 4
        for (int k = 0; k < 2 * S_TOP; k++) {
            float acc = 0.f;
            const float* w1row = w1 + k * S_TOP;
            #pragma unroll
            for (int j = 0; j < S_TOP; j++) acc = fmaf(sls[j], w1row[j], acc);
            // BN (eval mode) + ReLU
            float scale = bn_gamma[k] * rsqrtf(bn_var[k] + 1e-5f);
            acc = fmaf(acc - bn_mean[k], scale, bn_beta[k]);
            acc = fmaxf(acc, 0.f);
            l0 = fmaf(acc, w2[0 * 2 * S_TOP + k], l0);
            l1 = fmaf(acc, w2[1 * 2 * S_TOP + k], l1);
            l2 = fmaf(acc, w2[2 * 2 * S_TOP + k], l2);
        }
        float mx = fmaxf(l0, fmaxf(l1, l2));
        float e0 = __expf(l0 - mx), e1 = __expf(l1 - mx), e2 = __expf(l2 - mx);
        float inv = 1.0f / (e0 + e1 + e2);
        g_convk[t * 3 + 0] = e0 * inv;
        g_convk[t * 3 + 1] = e1 * inv;
        g_convk[t * 3 + 2] = e2 * inv;
    }
}

// ---------------------------------------------------------------------------
// Kernel 3: channel shift + depthwise temporal conv (k=3, zero pad).
// One thread per (segment of SEG frames, channel, float4 quad). Sliding
// 3-register window over s within the segment; per thread: SEG+2 coalesced
// float4 reads, SEG coalesced float4 writes.
// ---------------------------------------------------------------------------
__global__ void conv_kernel(const float* __restrict__ x, float* __restrict__ out) {
    int tid = blockIdx.x * blockDim.x + threadIdx.x;
    if (tid >= NSEG * NQUADS) return;
    int seg  = tid / NQUADS;
    int task = tid - seg * NQUADS;
    int c = task / HW4;
    int q = task - c * HW4;
    size_t base = (size_t)c * HW + (size_t)q * 4;   // float index, 16B aligned
    int t0 = seg * SEG;

    // channel shift: c<48 -> read x[s+1]; 48<=c<96 -> x[s-1]; else x[s]
    int d = (c < CNUM) ? 1 : ((c < 2 * CNUM) ? -1 : 0);

    float k0 = g_convk[c * 3 + 0];
    float k1 = g_convk[c * 3 + 1];
    float k2 = g_convk[c * 3 + 2];

    const float4 zero4 = make_float4(0.f, 0.f, 0.f, 0.f);
    auto ld = [&](int t) -> float4 {
        int ts = t + d;
        if ((unsigned)t < (unsigned)S_DIM && (unsigned)ts < (unsigned)S_DIM)
            return __ldcs(reinterpret_cast<const float4*>(x + (size_t)ts * CHW + base));
        return zero4;
    };

    float4 ym = ld(t0 - 1);   // y(t-1); zero when t0==0
    float4 yc = ld(t0);       // y(t)
    #pragma unroll
    for (int i = 0; i < SEG; i++) {
        int t = t0 + i;
        float4 yp = ld(t + 1);   // y(t+1); zero beyond the end
        float4 o;
        o.x = fmaf(k0, ym.x, fmaf(k1, yc.x, k2 * yp.x));
        o.y = fmaf(k0, ym.y, fmaf(k1, yc.y, k2 * yp.y));
        o.z = fmaf(k0, ym.z, fmaf(k1, yc.z, k2 * yp.z));
        o.w = fmaf(k0, ym.w, fmaf(k1, yc.w, k2 * yp.w));
        __stcs(reinterpret_cast<float4*>(out + (size_t)t * CHW + base), o);
        ym = yc; yc = yp;
    }
}

// ---------------------------------------------------------------------------
extern "C" void kernel_launch(void* const* d_in, const int* in_sizes, int n_in,
                              void* d_out, int out_size) {
    const float* x        = (const float*)d_in[0];
    const float* w_lin    = (const float*)d_in[1];
    const float* w1       = (const float*)d_in[2];
    const float* bn_gamma = (const float*)d_in[3];
    const float* bn_beta  = (const float*)d_in[4];
    const float* bn_mean  = (const float*)d_in[5];
    const float* bn_var   = (const float*)d_in[6];
    const float* w2       = (const float*)d_in[7];
    float* out            = (float*)d_out;

    pool_kernel<<<S_DIM * C_DIM, 128>>>(x);
    mlp_kernel<<<1, C_DIM>>>(w_lin, w1, bn_gamma, bn_beta, bn_mean, bn_var, w2);
    int threads = 256;
    int total = NSEG * NQUADS;
    conv_kernel<<<(total + threads - 1) / threads, threads>>>(x, out);
}

// round 5
// speedup vs baseline: 1.2481x; 1.0251x over previous
#include <cuda_runtime.h>
#include <cuda_bf16.h>

// Shapes (fixed per reference)
#define S_DIM   64
#define C_DIM   384
#define HW      3136          // 56*56
#define HW4     784           // HW/4 (float4 quads per channel plane)
#define CHW     (C_DIM * HW)  // 1204224 floats per frame
#define S_TOP   16
#define CNUM    48            // C_DIM / 8

#define SEG     16            // frames per conv segment
#define NSEG    (S_DIM / SEG) // 4
#define NQUADS  (C_DIM * HW4) // 301056 (c, quad) tasks
#define CONV_T  256           // conv block size
#define BLK_PER_SEG (NQUADS / CONV_T)  // 1176, exact

// Scratch (no device allocation allowed)
__device__ float g_xg[S_DIM * C_DIM];     // per-frame, per-channel means
__device__ float g_convk[C_DIM * 3];      // per-channel temporal kernel (softmaxed)

// ---------------------------------------------------------------------------
// Kernel 1: global average pool. One block per (s,c) plane of 3136 floats.
// ---------------------------------------------------------------------------
__global__ void pool_kernel(const float* __restrict__ x) {
    int plane = blockIdx.x;                 // = s*C_DIM + c (x is (s,c,h,w) contiguous)
    const float4* p = reinterpret_cast<const float4*>(x + (size_t)plane * HW);
    float sum = 0.f;
    for (int i = threadIdx.x; i < HW4; i += blockDim.x) {
        float4 v = __ldcs(p + i);           // streaming read: evict-first
        sum += (v.x + v.y) + (v.z + v.w);
    }
    // warp reduce
    #pragma unroll
    for (int off = 16; off > 0; off >>= 1)
        sum += __shfl_down_sync(0xFFFFFFFFu, sum, off);
    __shared__ float warp_sums[4];          // 128 threads = 4 warps
    int lane = threadIdx.x & 31, wid = threadIdx.x >> 5;
    if (lane == 0) warp_sums[wid] = sum;
    __syncthreads();
    if (threadIdx.x == 0) {
        float t = warp_sums[0] + warp_sums[1] + warp_sums[2] + warp_sums[3];
        g_xg[plane] = t * (1.0f / (float)HW);
    }
}

// ---------------------------------------------------------------------------
// Kernel 2: scores -> stable top-16 (temporal order) -> per-channel MLP ->
// softmax temporal kernel. Single block, 384 threads (12 warps).
// ---------------------------------------------------------------------------
__global__ void mlp_kernel(const float* __restrict__ w_lin,
                           const float* __restrict__ w1,
                           const float* __restrict__ bn_gamma,
                           const float* __restrict__ bn_beta,
                           const float* __restrict__ bn_mean,
                           const float* __restrict__ bn_var,
                           const float* __restrict__ w2) {
    __shared__ float sc[S_DIM];
    __shared__ int   flag[S_DIM];
    __shared__ int   idx[S_TOP];
    int t    = threadIdx.x;
    int lane = t & 31;
    int wid  = t >> 5;                      // 0..11

    // --- scores: xgs[s] = dot(xg[s,:], w_lin); one warp per frame ---
    for (int s = wid; s < S_DIM; s += 12) {
        const float* row = g_xg + s * C_DIM;
        float acc = 0.f;
        #pragma unroll
        for (int j = 0; j < C_DIM / 32; j++) {          // 12 elements per lane
            int c = lane + j * 32;
            acc = fmaf(row[c], w_lin[c], acc);
        }
        #pragma unroll
        for (int off = 16; off > 0; off >>= 1)
            acc += __shfl_down_sync(0xFFFFFFFFu, acc, off);
        if (lane == 0) sc[s] = acc;
    }
    __syncthreads();

    // --- stable rank: rank(i) = #{j : sc[j] > sc[i] or (== and j < i)} ---
    if (t < S_DIM) {
        float si = sc[t];
        int rank = 0;
        #pragma unroll 8
        for (int j = 0; j < S_DIM; j++) {
            float sj = sc[j];
            rank += (sj > si || (sj == si && j < t)) ? 1 : 0;
        }
        flag[t] = (rank < S_TOP) ? 1 : 0;
    }
    __syncthreads();
    if (t == 0) {                            // trivial 64-iter compaction
        int n = 0;
        for (int i = 0; i < S_DIM; i++)
            if (flag[i] && n < S_TOP) idx[n++] = i;
    }
    __syncthreads();

    // --- per-channel kernel-generating MLP ---
    if (t < C_DIM) {
        float sls[S_TOP];
        #pragma unroll
        for (int j = 0; j < S_TOP; j++) sls[j] = g_xg[idx[j] * C_DIM + t];

        float l0 = 0.f, l1 = 0.f, l2 = 0.f;
        #pragma unroll 4
        for (int k = 0; k < 2 * S_TOP; k++) {
            float acc = 0.f;
            const float* w1row = w1 + k * S_TOP;
            #pragma unroll
            for (int j = 0; j < S_TOP; j++) acc = fmaf(sls[j], w1row[j], acc);
            // BN (eval mode) + ReLU
            float scale = bn_gamma[k] * rsqrtf(bn_var[k] + 1e-5f);
            acc = fmaf(acc - bn_mean[k], scale, bn_beta[k]);
            acc = fmaxf(acc, 0.f);
            l0 = fmaf(acc, w2[0 * 2 * S_TOP + k], l0);
            l1 = fmaf(acc, w2[1 * 2 * S_TOP + k], l1);
            l2 = fmaf(acc, w2[2 * 2 * S_TOP + k], l2);
        }
        float mx = fmaxf(l0, fmaxf(l1, l2));
        float e0 = __expf(l0 - mx), e1 = __expf(l1 - mx), e2 = __expf(l2 - mx);
        float inv = 1.0f / (e0 + e1 + e2);
        g_convk[t * 3 + 0] = e0 * inv;
        g_convk[t * 3 + 1] = e1 * inv;
        g_convk[t * 3 + 2] = e2 * inv;
    }
}

// ---------------------------------------------------------------------------
// Kernel 3: channel shift + depthwise temporal conv (k=3, zero pad).
// Block mapping: seg is the FAST block dimension, so each scheduling wave
// covers all 4 segments of a contiguous (c,q) range. Halo frames (t0-1,
// t0+SEG) are then main-line reads of a same-wave neighbor block -> L2 hit
// instead of DRAM. x reads use default (cacheable) policy; out stores use
// __stcs (written once, never re-read).
// ---------------------------------------------------------------------------
__global__ void conv_kernel(const float* __restrict__ x, float* __restrict__ out) {
    int b     = blockIdx.x;
    int seg   = b & (NSEG - 1);              // fast dim: waves mix all segments
    int chunk = b >> 2;                      // 0 .. BLK_PER_SEG-1
    int task  = chunk * CONV_T + threadIdx.x;   // < NQUADS (exact multiple)
    int c = task / HW4;
    int q = task - c * HW4;
    size_t base = (size_t)c * HW + (size_t)q * 4;   // float index, 16B aligned
    int t0 = seg * SEG;

    // channel shift: c<48 -> read x[s+1]; 48<=c<96 -> x[s-1]; else x[s]
    int d = (c < CNUM) ? 1 : ((c < 2 * CNUM) ? -1 : 0);

    float k0 = g_convk[c * 3 + 0];
    float k1 = g_convk[c * 3 + 1];
    float k2 = g_convk[c * 3 + 2];

    const float4 zero4 = make_float4(0.f, 0.f, 0.f, 0.f);
    auto ld = [&](int t) -> float4 {
        int ts = t + d;
        if ((unsigned)t < (unsigned)S_DIM && (unsigned)ts < (unsigned)S_DIM)
            return *reinterpret_cast<const float4*>(x + (size_t)ts * CHW + base);
        return zero4;
    };

    float4 ym = ld(t0 - 1);   // y(t-1); zero when t0==0
    float4 yc = ld(t0);       // y(t)
    #pragma unroll
    for (int i = 0; i < SEG; i++) {
        int t = t0 + i;
        float4 yp = ld(t + 1);   // y(t+1); zero beyond the end
        float4 o;
        o.x = fmaf(k0, ym.x, fmaf(k1, yc.x, k2 * yp.x));
        o.y = fmaf(k0, ym.y, fmaf(k1, yc.y, k2 * yp.y));
        o.z = fmaf(k0, ym.z, fmaf(k1, yc.z, k2 * yp.z));
        o.w = fmaf(k0, ym.w, fmaf(k1, yc.w, k2 * yp.w));
        __stcs(reinterpret_cast<float4*>(out + (size_t)t * CHW + base), o);
        ym = yc; yc = yp;
    }
}

// ---------------------------------------------------------------------------
extern "C" void kernel_launch(void* const* d_in, const int* in_sizes, int n_in,
                              void* d_out, int out_size) {
    const float* x        = (const float*)d_in[0];
    const float* w_lin    = (const float*)d_in[1];
    const float* w1       = (const float*)d_in[2];
    const float* bn_gamma = (const float*)d_in[3];
    const float* bn_beta  = (const float*)d_in[4];
    const float* bn_mean  = (const float*)d_in[5];
    const float* bn_var   = (const float*)d_in[6];
    const float* w2       = (const float*)d_in[7];
    float* out            = (float*)d_out;

    pool_kernel<<<S_DIM * C_DIM, 128>>>(x);
    mlp_kernel<<<1, C_DIM>>>(w_lin, w1, bn_gamma, bn_beta, bn_mean, bn_var, w2);
    conv_kernel<<<NSEG * BLK_PER_SEG, CONV_T>>>(x, out);
}